// round 15
// baseline (speedup 1.0000x reference)
#include <cuda_runtime.h>
#include <cuda_fp16.h>
#include <string.h>

#define NN 50000
#define DD 128
#define CAP 128        // per-node bucket capacity; P(Poisson(12) > 128) ~ 1e-80

// bit-reinterpretation helpers
__device__ __forceinline__ unsigned h2_to_u(__half2 h) {
    unsigned u; memcpy(&u, &h, 4); return u;
}
__device__ __forceinline__ __half2 u_to_h2(unsigned u) {
    __half2 h; memcpy(&h, &u, 4); return h;
}
// packed fp32x2 helpers (Blackwell FFMA2 path)
__device__ __forceinline__ unsigned long long packf2(float lo, float hi) {
    unsigned long long r;
    asm("mov.b64 %0, {%1, %2};" : "=l"(r) : "f"(lo), "f"(hi));
    return r;
}
__device__ __forceinline__ void unpackf2(unsigned long long v, float& lo, float& hi) {
    asm("mov.b64 {%0, %1}, %2;" : "=f"(lo), "=f"(hi) : "l"(v));
}
__device__ __forceinline__ void ffma2p(unsigned long long& d,
                                       unsigned long long a, unsigned long long b) {
    asm("fma.rn.f32x2 %0, %1, %2, %0;" : "+l"(d) : "l"(a), "l"(b));
}

// scratch (static __device__ — zero-initialized at module load)
__device__ int   g_cnt[NN];
__device__ int   g_deg[NN];
__device__ float g_dinv[NN];
__device__ int   g_bucket[(size_t)NN * CAP];
__device__ __align__(16) __half g_xh[(size_t)NN * DD];
__device__ __align__(16) __half g_yh[(size_t)NN * DD];

// ---------------- prep + scatter fused ----------------
__global__ void k_prepscatter(const float* __restrict__ x, int nf4,
                              const int* __restrict__ src,
                              const int* __restrict__ dst, int e) {
    int i = blockIdx.x * blockDim.x + threadIdx.x;
    if (i < nf4) {
        float4 v = ((const float4*)x)[i];
        uint2 h;
        h.x = h2_to_u(__floats2half2_rn(v.x, v.y));
        h.y = h2_to_u(__floats2half2_rn(v.z, v.w));
        ((uint2*)g_xh)[i] = h;
    }
    int i0 = i * 4;
    if (i0 + 4 <= e) {
        int4 s4 = *(const int4*)(src + i0);
        int4 d4 = *(const int4*)(dst + i0);
        int p0 = -1, p1 = -1, p2 = -1, p3 = -1;
        if ((unsigned)s4.x < NN && (unsigned)d4.x < NN) p0 = atomicAdd(&g_cnt[d4.x], 1);
        if ((unsigned)s4.y < NN && (unsigned)d4.y < NN) p1 = atomicAdd(&g_cnt[d4.y], 1);
        if ((unsigned)s4.z < NN && (unsigned)d4.z < NN) p2 = atomicAdd(&g_cnt[d4.z], 1);
        if ((unsigned)s4.w < NN && (unsigned)d4.w < NN) p3 = atomicAdd(&g_cnt[d4.w], 1);
        if (p0 >= 0 && p0 < CAP) g_bucket[(size_t)d4.x * CAP + p0] = s4.x;
        if (p1 >= 0 && p1 < CAP) g_bucket[(size_t)d4.y * CAP + p1] = s4.y;
        if (p2 >= 0 && p2 < CAP) g_bucket[(size_t)d4.z * CAP + p2] = s4.z;
        if (p3 >= 0 && p3 < CAP) g_bucket[(size_t)d4.w * CAP + p3] = s4.w;
    } else if (i0 < e) {
        for (int j = i0; j < e; j++) {
            unsigned s = (unsigned)src[j], d = (unsigned)dst[j];
            if (s < NN && d < NN) {
                int p = atomicAdd(&g_cnt[d], 1);
                if (p < CAP) g_bucket[(size_t)d * CAP + p] = (int)s;
            }
        }
    }
}

// ---------------- dinv + degree snapshot + cursor re-arm ----------------
__global__ void k_dinv(int n) {
    int i = blockIdx.x * blockDim.x + threadIdx.x;
    if (i < n) {
        int c = g_cnt[i];
        g_deg[i] = c < CAP ? c : CAP;
        g_dinv[i] = rsqrtf((float)c + 1.0f);
        g_cnt[i] = 0;
    }
}

// ---------------- gather (fp16 x, packed fp32x2 accumulate, fp16 y out) ----------
__global__ void __launch_bounds__(256) k_agg_gather(int n) {
    __shared__ int   swidx[8 * 32];
    __shared__ float swnorm[8 * 32];
    int warp = (blockIdx.x * blockDim.x + threadIdx.x) >> 5;
    int wl   = (threadIdx.x >> 5) * 32;
    int lane = threadIdx.x & 31;
    if (warp >= n) return;
    int d = warp;

    float dd = g_dinv[d];
    float ss = dd * dd;
    uint2 sh = __ldg((const uint2*)g_xh + (size_t)d * 32 + lane);
    float2 sa = __half22float2(u_to_h2(sh.x));
    float2 sb = __half22float2(u_to_h2(sh.y));
    unsigned long long acc01 = packf2(sa.x * ss, sa.y * ss);
    unsigned long long acc23 = packf2(sb.x * ss, sb.y * ss);

    int deg = g_deg[d];
    const int* bkt = g_bucket + (size_t)d * CAP;
    int dq = deg < 32 ? deg : 32;

    if (lane < dq) {
        int s = __ldg(bkt + lane);
        swidx[wl + lane] = s;
        swnorm[wl + lane] = g_dinv[s] * dd;
    }
    __syncwarp();

    int e = 0;
    for (; e + 8 <= dq; e += 8) {
        uint2 v[8]; float nm[8];
        #pragma unroll
        for (int q = 0; q < 8; q++) {
            int s = swidx[wl + e + q];
            nm[q] = swnorm[wl + e + q];
            v[q] = __ldg((const uint2*)g_xh + (size_t)s * 32 + lane);
        }
        #pragma unroll
        for (int q = 0; q < 8; q++) {
            float2 a = __half22float2(u_to_h2(v[q].x));
            float2 b = __half22float2(u_to_h2(v[q].y));
            unsigned long long nm2 = packf2(nm[q], nm[q]);
            ffma2p(acc01, packf2(a.x, a.y), nm2);
            ffma2p(acc23, packf2(b.x, b.y), nm2);
        }
    }
    for (; e < dq; e++) {
        int s = swidx[wl + e];
        float nmv = swnorm[wl + e];
        uint2 v = __ldg((const uint2*)g_xh + (size_t)s * 32 + lane);
        float2 a = __half22float2(u_to_h2(v.x));
        float2 b = __half22float2(u_to_h2(v.y));
        unsigned long long nm2 = packf2(nmv, nmv);
        ffma2p(acc01, packf2(a.x, a.y), nm2);
        ffma2p(acc23, packf2(b.x, b.y), nm2);
    }
    for (int j = 32; j < deg; j++) {
        int s = __ldg(bkt + j);
        float nmv = g_dinv[s] * dd;
        uint2 v = __ldg((const uint2*)g_xh + (size_t)s * 32 + lane);
        float2 a = __half22float2(u_to_h2(v.x));
        float2 b = __half22float2(u_to_h2(v.y));
        unsigned long long nm2 = packf2(nmv, nmv);
        ffma2p(acc01, packf2(a.x, a.y), nm2);
        ffma2p(acc23, packf2(b.x, b.y), nm2);
    }
    float a0, a1, a2, a3;
    unpackf2(acc01, a0, a1);
    unpackf2(acc23, a2, a3);
    uint2 o;
    o.x = h2_to_u(__floats2half2_rn(a0, a1));
    o.y = h2_to_u(__floats2half2_rn(a2, a3));
    ((uint2*)g_yh)[(size_t)d * 32 + lane] = o;
}

// ---------------- persistent dual fp16 MMA GEMM, N-split for 2 CTAs/SM -----------
// CTA: 512 threads, 16 warps = 8m x 2n; computes BOTH layers for a 64-col N half.
#define BM   128
#define NH   64         // N columns per CTA
#define PH   136        // half pitch: 272B row stride, LDSM-aligned
#define GEMM_GRID 296   // 148 SMs x 2 halves

__device__ __forceinline__ void mma_f16(float* c, const unsigned* a,
                                        unsigned b0, unsigned b1) {
    asm volatile(
        "mma.sync.aligned.m16n8k16.row.col.f32.f16.f16.f32 "
        "{%0,%1,%2,%3}, {%4,%5,%6,%7}, {%8,%9}, {%0,%1,%2,%3};"
        : "+f"(c[0]), "+f"(c[1]), "+f"(c[2]), "+f"(c[3])
        : "r"(a[0]), "r"(a[1]), "r"(a[2]), "r"(a[3]), "r"(b0), "r"(b1));
}

__device__ __forceinline__ void ldsm_x4(unsigned& r0, unsigned& r1,
                                        unsigned& r2, unsigned& r3, unsigned addr) {
    asm volatile("ldmatrix.sync.aligned.m8n8.x4.shared.b16 {%0,%1,%2,%3}, [%4];"
        : "=r"(r0), "=r"(r1), "=r"(r2), "=r"(r3) : "r"(addr));
}

__device__ __forceinline__ void cp_async16(unsigned d, const void* s, int src_bytes) {
    asm volatile("cp.async.cg.shared.global [%0], [%1], 16, %2;"
        :: "r"(d), "l"(s), "r"(src_bytes) : "memory");
}
__device__ __forceinline__ void cp_commit() {
    asm volatile("cp.async.commit_group;" ::: "memory");
}
__device__ __forceinline__ void cp_wait0() {
    asm volatile("cp.async.wait_group 0;" ::: "memory");
}

__global__ void __launch_bounds__(512, 2)
k_gemm(const float* __restrict__ W1, const float* __restrict__ b1,
       const float* __restrict__ W2, const float* __restrict__ b2,
       float* __restrict__ out, int n, int ntiles) {
    extern __shared__ __half smh[];
    __half* W1h = smh;                       // [NH][k]: 64 x PH
    __half* W2h = smh + NH * PH;             // 64 x PH
    __half* Ys0 = smh + 2 * NH * PH;         // BM x PH (buffer 0)
    __half* Ys1 = Ys0 + BM * PH;             // BM x PH (buffer 1)

    int tid  = threadIdx.x;
    int lane = tid & 31;
    int wid  = tid >> 5;
    int wm = wid >> 1, wn = wid & 1;         // 8m x 2n
    int g  = lane >> 2, tig = lane & 3;
    int nhalf = blockIdx.x & 1;
    int n0 = nhalf * NH;                     // this CTA's first output column

    unsigned ysb[2];
    ysb[0] = (unsigned)__cvta_generic_to_shared(Ys0);
    ysb[1] = (unsigned)__cvta_generic_to_shared(Ys1);

    // stage this CTA's W half, transposed to [n][k]; float4 gmem loads
    // W row-major [k=128][n=128]; our cols are [n0, n0+64)
    for (int i = tid; i < 128 * 16; i += 512) {        // 16 float4 chunks per k-row
        int k = i >> 4, c4 = (i & 15) * 4;             // 4 consecutive n within the half
        float4 v1 = __ldg((const float4*)(W1 + k * 128 + n0 + c4));
        float4 v2 = __ldg((const float4*)(W2 + k * 128 + n0 + c4));
        W1h[(c4 + 0) * PH + k] = __float2half(v1.x);
        W1h[(c4 + 1) * PH + k] = __float2half(v1.y);
        W1h[(c4 + 2) * PH + k] = __float2half(v1.z);
        W1h[(c4 + 3) * PH + k] = __float2half(v1.w);
        W2h[(c4 + 0) * PH + k] = __float2half(v2.x);
        W2h[(c4 + 1) * PH + k] = __float2half(v2.y);
        W2h[(c4 + 2) * PH + k] = __float2half(v2.z);
        W2h[(c4 + 3) * PH + k] = __float2half(v2.w);
    }

    // hoisted biases: 4 nt x 2 cols per layer
    float hb1[4][2], hb2[4][2];
    #pragma unroll
    for (int nt = 0; nt < 4; nt++) {
        int col = n0 + wn * 32 + nt * 8 + 2 * tig;
        hb1[nt][0] = __ldg(b1 + col); hb1[nt][1] = __ldg(b1 + col + 1);
        hb2[nt][0] = __ldg(b2 + col); hb2[nt][1] = __ldg(b2 + col + 1);
    }

    // ldmatrix lane offsets
    // A (x4): m16 rows at wm*16; lanes 0-15 rows, lanes>=16 k+8
    unsigned aOff = (unsigned)(((wm * 16 + (lane & 15)) * PH + ((lane >> 4) ? 8 : 0)) * 2);
    // B (x4): mat0/1 = W1h (k0,k0+8), mat2/3 = W2h; per nt
    unsigned bAddr[4];
    #pragma unroll
    for (int nt = 0; nt < 4; nt++) {
        int nrow = wn * 32 + nt * 8 + (lane & 7);
        int koff = ((lane >> 3) & 1) ? 8 : 0;
        const __half* base = (lane < 16) ? W1h : W2h;
        bAddr[nt] = (unsigned)__cvta_generic_to_shared(base) +
                    (unsigned)((nrow * PH + koff) * 2);
    }

    auto stage = [&](int tile, int buf) {
        int m0 = tile * BM;
        #pragma unroll
        for (int i = tid; i < BM * 16; i += 512) {
            int row = i >> 4, c16 = i & 15;
            int gg = m0 + row;
            unsigned dstd = ysb[buf] + (unsigned)((row * PH + c16 * 8) * 2);
            const void* srcp = (const void*)((const uint4*)g_yh + (size_t)(gg < n ? gg : 0) * 16 + c16);
            cp_async16(dstd, srcp, gg < n ? 16 : 0);
        }
        cp_commit();
    };

    int buf = 0;
    int t0 = blockIdx.x >> 1;               // tile stride 148 over both halves
    if (t0 < ntiles) stage(t0, 0);

    for (int tile = t0; tile < ntiles; tile += 148) {
        int nxt = tile + 148;
        cp_wait0();
        __syncthreads();
        if (nxt < ntiles) stage(nxt, buf ^ 1);

        float acc1[4][4], acc2[4][4];
        #pragma unroll
        for (int nt = 0; nt < 4; nt++)
            #pragma unroll
            for (int q = 0; q < 4; q++) { acc1[nt][q] = 0.f; acc2[nt][q] = 0.f; }

        unsigned yb = ysb[buf];
        #pragma unroll
        for (int ks = 0; ks < 8; ks++) {
            unsigned kb = ks * 32;
            unsigned a[4];
            ldsm_x4(a[0], a[1], a[2], a[3], yb + aOff + kb);
            #pragma unroll
            for (int nt = 0; nt < 4; nt++) {
                unsigned w1b0, w1b1, w2b0, w2b1;
                ldsm_x4(w1b0, w1b1, w2b0, w2b1, bAddr[nt] + kb);
                mma_f16(acc1[nt], a, w1b0, w1b1);
                mma_f16(acc2[nt], a, w2b0, w2b1);
            }
        }

        int m0 = tile * BM;
        int r0 = m0 + wm * 16 + g;
        #pragma unroll
        for (int nt = 0; nt < 4; nt++) {
            int col = n0 + wn * 32 + nt * 8 + 2 * tig;
            if (r0 < n) {
                float2 o;
                o.x = 0.5f * (fmaxf(acc1[nt][0] + hb1[nt][0], 0.f) +
                              fmaxf(acc2[nt][0] + hb2[nt][0], 0.f));
                o.y = 0.5f * (fmaxf(acc1[nt][1] + hb1[nt][1], 0.f) +
                              fmaxf(acc2[nt][1] + hb2[nt][1], 0.f));
                *(float2*)(out + (size_t)r0 * 128 + col) = o;
            }
            if (r0 + 8 < n) {
                float2 o;
                o.x = 0.5f * (fmaxf(acc1[nt][2] + hb1[nt][0], 0.f) +
                              fmaxf(acc2[nt][2] + hb2[nt][0], 0.f));
                o.y = 0.5f * (fmaxf(acc1[nt][3] + hb1[nt][1], 0.f) +
                              fmaxf(acc2[nt][3] + hb2[nt][1], 0.f));
                *(float2*)(out + (size_t)(r0 + 8) * 128 + col) = o;
            }
        }
        __syncthreads();
        buf ^= 1;
    }
}

extern "C" void kernel_launch(void* const* d_in, const int* in_sizes, int n_in,
                              void* d_out, int out_size) {
    const float* x  = (const float*)d_in[0];
    const int*   ei = (const int*)d_in[1];
    const float* W1 = (const float*)d_in[2];
    const float* b1 = (const float*)d_in[3];
    const float* W2 = (const float*)d_in[4];
    const float* b2 = (const float*)d_in[5];
    float* out = (float*)d_out;

    int n_nodes = in_sizes[0] / DD;       // 50000
    int n_edges = in_sizes[1] / 2;        // 600000
    const int* src = ei;
    const int* dst = ei + n_edges;

    int nb_nodes = (n_nodes + 255) / 256;
    int nf4      = n_nodes * 32;
    int nb_prep  = (nf4 + 255) / 256;

    k_prepscatter<<<nb_prep, 256>>>(x, nf4, src, dst, n_edges);
    k_dinv<<<nb_nodes, 256>>>(n_nodes);
    {
        int blocks = (n_nodes * 32 + 255) / 256;
        k_agg_gather<<<blocks, 256>>>(n_nodes);
    }
    {
        int smem_bytes = (2 * NH * PH + 2 * BM * PH) * 2;   // 104448
        cudaFuncSetAttribute(k_gemm,
                             cudaFuncAttributeMaxDynamicSharedMemorySize, smem_bytes);
        int ntiles = (n_nodes + BM - 1) / BM;
        k_gemm<<<GEMM_GRID, 512, smem_bytes>>>(W1, b1, W2, b2, out, n_nodes, ntiles);
    }
}